// round 11
// baseline (speedup 1.0000x reference)
#include <cuda_runtime.h>
#include <cuda_bf16.h>
#include <cstdint>
#include <math.h>

#define DM 1024
#define NH 16
#define HD 64
#define NB 2
#define SQ 2048
#define MTOT (NB*SQ)   // 4096

// ================= mma.sync helpers =================
__device__ __forceinline__ uint32_t smem_u32(const void* p) {
    uint32_t a;
    asm("{ .reg .u64 t; cvta.to.shared.u64 t, %1; cvt.u32.u64 %0, t; }" : "=r"(a) : "l"(p));
    return a;
}
__device__ __forceinline__ void ldm_x4(uint32_t* r, uint32_t addr) {
    asm volatile("ldmatrix.sync.aligned.m8n8.x4.shared.b16 {%0,%1,%2,%3}, [%4];"
                 : "=r"(r[0]), "=r"(r[1]), "=r"(r[2]), "=r"(r[3]) : "r"(addr));
}
__device__ __forceinline__ void mma_bf16(float* d, const uint32_t* a, const uint32_t* b) {
    asm volatile("mma.sync.aligned.m16n8k16.row.col.f32.bf16.bf16.f32 "
                 "{%0,%1,%2,%3}, {%4,%5,%6,%7}, {%8,%9}, {%0,%1,%2,%3};"
                 : "+f"(d[0]), "+f"(d[1]), "+f"(d[2]), "+f"(d[3])
                 : "r"(a[0]), "r"(a[1]), "r"(a[2]), "r"(a[3]), "r"(b[0]), "r"(b[1]));
}
__device__ __forceinline__ void mma_tf32(float* d, const uint32_t* a, const uint32_t* b) {
    asm volatile("mma.sync.aligned.m16n8k8.row.col.f32.tf32.tf32.f32 "
                 "{%0,%1,%2,%3}, {%4,%5,%6,%7}, {%8,%9}, {%0,%1,%2,%3};"
                 : "+f"(d[0]), "+f"(d[1]), "+f"(d[2]), "+f"(d[3])
                 : "r"(a[0]), "r"(a[1]), "r"(a[2]), "r"(a[3]), "r"(b[0]), "r"(b[1]));
}
__device__ __forceinline__ void mma_s8(int* d, const uint32_t* a, const uint32_t* b) {
    asm volatile("mma.sync.aligned.m16n8k32.row.col.s32.s8.s8.s32 "
                 "{%0,%1,%2,%3}, {%4,%5,%6,%7}, {%8,%9}, {%0,%1,%2,%3};"
                 : "+r"(d[0]), "+r"(d[1]), "+r"(d[2]), "+r"(d[3])
                 : "r"(a[0]), "r"(a[1]), "r"(a[2]), "r"(a[3]), "r"(b[0]), "r"(b[1]));
}
__device__ __forceinline__ uint32_t cvt_tf32(float x) {
    uint32_t r; asm("cvt.rna.tf32.f32 %0, %1;" : "=r"(r) : "f"(x)); return r;
}
__device__ __forceinline__ void cp_async16(uint32_t saddr, const void* gaddr) {
    asm volatile("cp.async.cg.shared.global [%0], [%1], 16;" :: "r"(saddr), "l"(gaddr));
}
#define CP_COMMIT() asm volatile("cp.async.commit_group;")
#define CP_WAIT1()  asm volatile("cp.async.wait_group 1;")
#define CP_WAIT0()  asm volatile("cp.async.wait_group 0;")
#define SW128(off) ((off) ^ (((off) >> 3) & 0x70))
__device__ __forceinline__ uint32_t pack_bf16x2(float x, float y) {
    __nv_bfloat162 t = __floats2bfloat162_rn(x, y);
    return *(uint32_t*)&t;
}

// ================= scratch =================
__device__ int8_t g_twi[4][DM*DM];           // ternary weights int8 {-1,0,1}
__device__ int8_t g_aq[MTOT*3*DM];           // 3-limb int8 query (reused for out-proj input)
__device__ int8_t g_ak[MTOT*3*DM];
__device__ int8_t g_av[MTOT*3*DM];
__device__ float  g_qb[MTOT*DM];
__device__ float  g_kb[MTOT*DM];
__device__ float  g_vb[MTOT*DM];
__device__ float  g_ab[MTOT*DM];
__device__ double g_part[4][32];
// fragment-layout operands for flash attention
__device__ uint32_t g_qfhi[512*8192];   // [(b*16+qt)*16+h] tiles: [ks8][w8][lane32][r4]
__device__ uint32_t g_qflo[512*8192];
__device__ uint32_t g_kfhi[1024*4096];  // [(b*16+h)*32+kt] tiles: [ks8][n8][lane32][r2]
__device__ uint32_t g_kflo[1024*4096];
__device__ uint32_t g_vfhi[1024*2048];  // [(b*16+h)*32+kt] tiles: [j4][n8][lane32][r2]
__device__ uint32_t g_vflo[1024*2048];

// ================= 3-limb int8 residual quantizer (power-of-2 scales) =================
// x ~ a0/e0 + a1/(128 e0) + a2/(16384 e0); deterministic, clamped.
__device__ __forceinline__ void quant3(float x, float e0, float inv_e0,
                                       int& a0, int& a1, int& a2) {
    float c0 = fminf(fmaxf(x * e0, -127.f), 127.f);
    a0 = __float2int_rn(c0);
    float r0 = x - (float)a0 * inv_e0;
    float c1 = fminf(fmaxf(r0 * (e0 * 128.f), -127.f), 127.f);
    a1 = __float2int_rn(c1);
    float r1 = r0 - (float)a1 * (inv_e0 * (1.f / 128.f));
    float c2 = fminf(fmaxf(r1 * (e0 * 16384.f), -127.f), 127.f);
    a2 = __float2int_rn(c2);
}
__device__ __forceinline__ void quant3_store(const float4& x, int8_t* base, int j,
                                             float e0, float inv_e0) {
    int a0[4], a1[4], a2[4];
    quant3(x.x, e0, inv_e0, a0[0], a1[0], a2[0]);
    quant3(x.y, e0, inv_e0, a0[1], a1[1], a2[1]);
    quant3(x.z, e0, inv_e0, a0[2], a1[2], a2[2]);
    quant3(x.w, e0, inv_e0, a0[3], a1[3], a2[3]);
    *(char4*)(base + j)        = make_char4((char)a0[0], (char)a0[1], (char)a0[2], (char)a0[3]);
    *(char4*)(base + 1024 + j) = make_char4((char)a1[0], (char)a1[1], (char)a1[2], (char)a1[3]);
    *(char4*)(base + 2048 + j) = make_char4((char)a2[0], (char)a2[1], (char)a2[2], (char)a2[3]);
}

// ================= prep: abs-mean partials + input quantization (one launch) ==========
__global__ void prep_k(const float* __restrict__ Q, const float* __restrict__ K,
                       const float* __restrict__ V,
                       const float* __restrict__ w0, const float* __restrict__ w1,
                       const float* __restrict__ w2, const float* __restrict__ w3) {
    __shared__ double sred[256];
    const int z = blockIdx.y;
    if (z == 3) {
        if (blockIdx.x >= 128) return;
        int mid = blockIdx.x >> 5, blk = blockIdx.x & 31;
        const float* w = (mid == 0) ? w0 : (mid == 1) ? w1 : (mid == 2) ? w2 : w3;
        const int chunk = (DM * DM) / 32;
        const float* p = w + blk * chunk;
        double acc = 0.0;
        for (int i = threadIdx.x; i < chunk; i += blockDim.x) acc += (double)fabsf(p[i]);
        sred[threadIdx.x] = acc;
        __syncthreads();
        for (int s = 128; s > 0; s >>= 1) {
            if (threadIdx.x < s) sred[threadIdx.x] += sred[threadIdx.x + s];
            __syncthreads();
        }
        if (threadIdx.x == 0) g_part[mid][blk] = sred[0];
        return;
    }
    const float* X = (z == 0) ? Q : (z == 1) ? K : V;
    int8_t* dst = (z == 0) ? g_aq : (z == 1) ? g_ak : g_av;
    int i = blockIdx.x * blockDim.x + threadIdx.x;
    int m = i >> 8, j = (i & 255) * 4;
    float4 x = ((const float4*)X)[i];
    quant3_store(x, dst + (size_t)m * 3072, j, 16.f, 0.0625f);
}

// ================= ternarize (final reduction folded in) =================
__global__ void ternarize_k(const float* __restrict__ w0, const float* __restrict__ w1,
                            const float* __restrict__ w2, const float* __restrict__ w3) {
    int idx = blockIdx.x * blockDim.x + threadIdx.x;
    int mid = idx >> 20, off = idx & ((1 << 20) - 1);
    const float* w = (mid == 0) ? w0 : (mid == 1) ? w1 : (mid == 2) ? w2 : w3;
    __shared__ float s_thr;
    if (threadIdx.x == 0) {
        double s = 0.0;
#pragma unroll
        for (int i = 0; i < 32; i++) s += g_part[mid][i];
        s_thr = (float)(s / (double)(DM * DM));
    }
    __syncthreads();
    float t = s_thr;
    float x = w[off];
    g_twi[mid][off] = (fabsf(x) > t) ? (x > 0.f ? (int8_t)1 : (int8_t)-1) : (int8_t)0;
}

// out-proj input quantization (g_ab fp32 -> g_aq 3 int8 limbs, e0 = 1)
__global__ void quant2_k() {
    int i = blockIdx.x * blockDim.x + threadIdx.x;
    int m = i >> 8, j = (i & 255) * 4;
    float4 x = ((const float4*)g_ab)[i];
    quant3_store(x, g_aq + (size_t)m * 3072, j, 1.f, 1.f);
}

// ================= int8 GEMM: C[M,1024] = sum_l s_l (A_l[M,1024] @ W^T), IMMA k32 ======
// A: [m][limb*1024 + k] int8 (3 limbs contiguous => 3072 B streamed sequentially).
// W: [out][k] int8 ternary. BK = 128 bytes, 24 iters, exact int32 acc with <<7 at limb
// boundaries: acc_final = C0*2^14 + C1*2^7 + C2; C = acc * scale (scale = s0^2-ish pow2).
__device__ __forceinline__ void gemm_body_i8(const int8_t* __restrict__ A,
                                             const int8_t* __restrict__ W,
                                             float* __restrict__ C,
                                             float scale, char* smraw) {
    const int tid = threadIdx.x, lane = tid & 31, wid = tid >> 5;
    const int wm = (wid >> 2) * 64, wn = (wid & 3) * 32;
    const int row0 = blockIdx.y * 128, col0 = blockIdx.x * 128;
    const uint32_t sbase = smem_u32(smraw);

    int acc[4][4][4];
#pragma unroll
    for (int i = 0; i < 4; i++)
#pragma unroll
        for (int j = 0; j < 4; j++)
#pragma unroll
            for (int k = 0; k < 4; k++) acc[i][j][k] = 0;

    const int NIT = 24;   // 3 limbs x 8 chunks of 128 bytes

#pragma unroll 1
    for (int pre = 0; pre < 2; pre++) {
        const uint32_t sa = sbase + pre * 32768u;
        const uint32_t sb = sa + 16384u;
#pragma unroll
        for (int j = 0; j < 4; j++) {
            int c = tid * 4 + j;
            int r = c >> 3, g = c & 7;
            cp_async16(sa + SW128(r * 128 + g * 16), A + (size_t)(row0 + r) * 3072 + pre * 128 + g * 16);
            cp_async16(sb + SW128(r * 128 + g * 16), W + (size_t)(col0 + r) * 1024 + (pre & 7) * 128 + g * 16);
        }
        CP_COMMIT();
    }

    for (int it = 0; it < NIT; it++) {
        CP_WAIT1();
        __syncthreads();
        const uint32_t sa = sbase + (it & 1) * 32768u;
        const uint32_t sb = sa + 16384u;
#pragma unroll
        for (int ks = 0; ks < 4; ks++) {   // 4 x k32 = 128 bytes
            uint32_t a[4][4];
#pragma unroll
            for (int mi = 0; mi < 4; mi++)
                ldm_x4(a[mi], sa + SW128((wm + mi * 16 + (lane & 15)) * 128 +
                                         (2 * ks + (lane >> 4)) * 16));
            uint32_t b[2][4];
#pragma unroll
            for (int p = 0; p < 2; p++)
                ldm_x4(b[p], sb + SW128((wn + p * 16 + ((lane >> 4) << 3) + (lane & 7)) * 128 +
                                        (2 * ks + ((lane >> 3) & 1)) * 16));
#pragma unroll
            for (int mi = 0; mi < 4; mi++)
#pragma unroll
                for (int ni = 0; ni < 4; ni++)
                    mma_s8(acc[mi][ni], a[mi], &b[ni >> 1][(ni & 1) * 2]);
        }
        if (it == 7 || it == 15) {   // limb boundary: fold scale 2^-7 into int acc
#pragma unroll
            for (int mi = 0; mi < 4; mi++)
#pragma unroll
                for (int ni = 0; ni < 4; ni++)
#pragma unroll
                    for (int k = 0; k < 4; k++) acc[mi][ni][k] <<= 7;
        }
        __syncthreads();
        if (it + 2 < NIT) {
            const int it2 = it + 2;
            const uint32_t sa2 = sbase + (it2 & 1) * 32768u;
            const uint32_t sb2 = sa2 + 16384u;
#pragma unroll
            for (int j = 0; j < 4; j++) {
                int c = tid * 4 + j;
                int r = c >> 3, g = c & 7;
                cp_async16(sa2 + SW128(r * 128 + g * 16), A + (size_t)(row0 + r) * 3072 + it2 * 128 + g * 16);
                cp_async16(sb2 + SW128(r * 128 + g * 16), W + (size_t)(col0 + r) * 1024 + (it2 & 7) * 128 + g * 16);
            }
            CP_COMMIT();
        }
    }

#pragma unroll
    for (int mi = 0; mi < 4; mi++)
#pragma unroll
        for (int ni = 0; ni < 4; ni++) {
            int r = row0 + wm + mi * 16 + (lane >> 2);
            int c = col0 + wn + ni * 8 + 2 * (lane & 3);
            *(float2*)&C[(size_t)r * DM + c] =
                make_float2((float)acc[mi][ni][0] * scale, (float)acc[mi][ni][1] * scale);
            *(float2*)&C[(size_t)(r + 8) * DM + c] =
                make_float2((float)acc[mi][ni][2] * scale, (float)acc[mi][ni][3] * scale);
        }
}

// mega GEMM: z=0 q -> g_qb, z=1 k -> g_kb, z=2 v -> g_vb  (input scale s0=2^-4 => 2^-18)
__global__ __launch_bounds__(256, 2) void gemm_qkv() {
    extern __shared__ char smraw[];
    const int z = blockIdx.z;
    const int8_t* A = (z == 0) ? g_aq : (z == 1) ? g_ak : g_av;
    float* C = (z == 0) ? g_qb : (z == 1) ? g_kb : g_vb;
    gemm_body_i8(A, g_twi[z], C, 3.814697265625e-06f /* 2^-18 */, smraw);
}
// output projection GEMM (s0 = 1 => scale 2^-14)
__global__ __launch_bounds__(256, 2) void gemm_out(float* __restrict__ out) {
    extern __shared__ char smraw[];
    gemm_body_i8(g_aq, g_twi[3], out, 6.103515625e-05f /* 2^-14 */, smraw);
}

// ================= merged fragment writer (unchanged math) =================
// grid (32, 16, 6): z = kind*2 + b, kind 0=Q (x<16), 1=K, 2=V; y = head
__global__ __launch_bounds__(256) void frag_writer() {
    __shared__ float tile[128 * 65];
    const int kind = blockIdx.z >> 1, b = blockIdx.z & 1;
    const int h = blockIdx.y;
    const int tid = threadIdx.x;

    if (kind == 0) {
        const int qt = blockIdx.x;
        if (qt >= 16) return;
        for (int idx = tid; idx < 128 * 64; idx += 256) {
            int row = idx >> 6, col = idx & 63;
            tile[row * 65 + col] = g_qb[(size_t)(b * SQ + qt * 128 + row) * DM + h * HD + col];
        }
        __syncthreads();
        size_t base = (size_t)((b * 16 + qt) * 16 + h) * 8192;
        for (int t2 = tid; t2 < 8192; t2 += 256) {
            int r = t2 & 3, lane = (t2 >> 2) & 31, w = (t2 >> 7) & 7, ks = (t2 >> 10) & 7;
            int g = lane >> 2, tig = lane & 3;
            int row = w * 16 + g + 8 * (r & 1);
            int col = ks * 8 + tig + 4 * (r >> 1);
            float v = tile[row * 65 + col] * 0.125f;
            uint32_t hi = cvt_tf32(v);
            g_qfhi[base + t2] = hi;
            g_qflo[base + t2] = cvt_tf32(v - __uint_as_float(hi));
        }
    } else if (kind == 1) {
        const int kt = blockIdx.x;
        for (int idx = tid; idx < 64 * 64; idx += 256) {
            int row = idx >> 6, col = idx & 63;
            tile[row * 65 + col] = g_kb[(size_t)(b * SQ + kt * 64 + row) * DM + h * HD + col];
        }
        __syncthreads();
        size_t base = (size_t)((b * 16 + h) * 32 + kt) * 4096;
        for (int t2 = tid; t2 < 4096; t2 += 256) {
            int r = t2 & 1, lane = (t2 >> 1) & 31, n = (t2 >> 6) & 7, ks = (t2 >> 9) & 7;
            int g = lane >> 2, tig = lane & 3;
            int key = n * 8 + g;
            int d = ks * 8 + tig + 4 * r;
            float v = tile[key * 65 + d];
            uint32_t hi = cvt_tf32(v);
            g_kfhi[base + t2] = hi;
            g_kflo[base + t2] = cvt_tf32(v - __uint_as_float(hi));
        }
    } else {
        const int kt = blockIdx.x;
        for (int idx = tid; idx < 64 * 64; idx += 256) {
            int row = idx >> 6, col = idx & 63;
            tile[row * 65 + col] = g_vb[(size_t)(b * SQ + kt * 64 + row) * DM + h * HD + col];
        }
        __syncthreads();
        size_t base = (size_t)((b * 16 + h) * 32 + kt) * 2048;
        for (int t2 = tid; t2 < 2048; t2 += 256) {
            int r = t2 & 1, lane = (t2 >> 1) & 31, n = (t2 >> 6) & 7, j = (t2 >> 9) & 3;
            int g = lane >> 2, tig = lane & 3;
            int key0 = j * 16 + 2 * tig + 8 * r;
            int d = n * 8 + g;
            float v0 = tile[key0 * 65 + d];
            float v1 = tile[(key0 + 1) * 65 + d];
            float h0 = __bfloat162float(__float2bfloat16(v0));
            float h1 = __bfloat162float(__float2bfloat16(v1));
            g_vfhi[base + t2] = pack_bf16x2(v0, v1);
            g_vflo[base + t2] = pack_bf16x2(v0 - h0, v1 - h1);
        }
    }
}

// ================= flash attention (R6-proven, unchanged) ======================
#define FOFF_QHI 0u
#define FOFF_QLO 32768u
#define FOFF_ST  65536u
#define FSTAGE   49152u
#define FOFF_KHI 0u
#define FOFF_KLO 16384u
#define FOFF_VHI 32768u
#define FOFF_VLO 40960u
__global__ __launch_bounds__(256) void flash_mma2() {
    extern __shared__ char smraw[];
    const uint32_t sbase = smem_u32(smraw);
    const int qt = blockIdx.x, h = blockIdx.y, b = blockIdx.z;
    const int tid = threadIdx.x, lane = tid & 31, wid = tid >> 5;
    const int g = lane >> 2, tig = lane & 3;

    const uint32_t* Qhi = g_qfhi + (size_t)((b * 16 + qt) * 16 + h) * 8192;
    const uint32_t* Qlo = g_qflo + (size_t)((b * 16 + qt) * 16 + h) * 8192;
    const uint32_t* Khi = g_kfhi + (size_t)((b * 16 + h) * 32) * 4096;
    const uint32_t* Klo = g_kflo + (size_t)((b * 16 + h) * 32) * 4096;
    const uint32_t* Vhi = g_vfhi + (size_t)((b * 16 + h) * 32) * 2048;
    const uint32_t* Vlo = g_vflo + (size_t)((b * 16 + h) * 32) * 2048;

#pragma unroll
    for (int i = 0; i < 8; i++) {
        int idx = tid + i * 256;
        cp_async16(sbase + FOFF_QHI + idx * 16, Qhi + idx * 4);
        cp_async16(sbase + FOFF_QLO + idx * 16, Qlo + idx * 4);
    }
    CP_COMMIT();

    {
        const uint32_t st = sbase + FOFF_ST;
#pragma unroll
        for (int i = 0; i < 4; i++) {
            int idx = tid + i * 256;
            cp_async16(st + FOFF_KHI + idx * 16, Khi + idx * 4);
            cp_async16(st + FOFF_KLO + idx * 16, Klo + idx * 4);
        }
#pragma unroll
        for (int i = 0; i < 2; i++) {
            int idx = tid + i * 256;
            cp_async16(st + FOFF_VHI + idx * 16, Vhi + idx * 4);
            cp_async16(st + FOFF_VLO + idx * 16, Vlo + idx * 4);
        }
        CP_COMMIT();
    }

    float o[8][4];
#pragma unroll
    for (int n = 0; n < 8; n++)
#pragma unroll
        for (int k = 0; k < 4; k++) o[n][k] = 0.f;
    float m0 = -1e30f, m1 = -1e30f, l0 = 0.f, l1 = 0.f;

    for (int t = 0; t < 32; t++) {
        CP_WAIT0();
        __syncthreads();
        if (t + 1 < 32) {
            const uint32_t st = sbase + FOFF_ST + ((t + 1) & 1) * FSTAGE;
            const uint32_t* kh = Khi + (size_t)(t + 1) * 4096;
            const uint32_t* kl = Klo + (size_t)(t + 1) * 4096;
            const uint32_t* vh = Vhi + (size_t)(t + 1) * 2048;
            const uint32_t* vl = Vlo + (size_t)(t + 1) * 2048;
#pragma unroll
            for (int i = 0; i < 4; i++) {
                int idx = tid + i * 256;
                cp_async16(st + FOFF_KHI + idx * 16, kh + idx * 4);
                cp_async16(st + FOFF_KLO + idx * 16, kl + idx * 4);
            }
#pragma unroll
            for (int i = 0; i < 2; i++) {
                int idx = tid + i * 256;
                cp_async16(st + FOFF_VHI + idx * 16, vh + idx * 4);
                cp_async16(st + FOFF_VLO + idx * 16, vl + idx * 4);
            }
            CP_COMMIT();
        }
        const uint32_t soff = FOFF_ST + (t & 1) * FSTAGE;

        float sf[8][4];
#pragma unroll
        for (int n = 0; n < 8; n++)
#pragma unroll
            for (int k = 0; k < 4; k++) sf[n][k] = 0.f;
#pragma unroll
        for (int ks = 0; ks < 8; ks++) {
            uint4 qa = *(const uint4*)(smraw + FOFF_QHI + ((ks * 8 + wid) * 32 + lane) * 16);
            uint4 ql = *(const uint4*)(smraw + FOFF_QLO + ((ks * 8 + wid) * 32 + lane) * 16);
            uint32_t ah[4] = {qa.x, qa.y, qa.z, qa.w};
            uint32_t al[4] = {ql.x, ql.y, ql.z, ql.w};
#pragma unroll
            for (int n = 0; n < 8; n++) {
                uint2 bh2 = *(const uint2*)(smraw + soff + FOFF_KHI + ((ks * 8 + n) * 32 + lane) * 8);
                uint2 bl2 = *(const uint2*)(smraw + soff + FOFF_KLO + ((ks * 8 + n) * 32 + lane) * 8);
                uint32_t bh[2] = {bh2.x, bh2.y};
                uint32_t bl[2] = {bl2.x, bl2.y};
                mma_tf32(sf[n], ah, bh);
                mma_tf32(sf[n], ah, bl);
                mma_tf32(sf[n], al, bh);
            }
        }

        float mx0 = -1e30f, mx1 = -1e30f;
#pragma unroll
        for (int n = 0; n < 8; n++) {
            mx0 = fmaxf(mx0, fmaxf(sf[n][0], sf[n][1]));
            mx1 = fmaxf(mx1, fmaxf(sf[n][2], sf[n][3]));
        }
        mx0 = fmaxf(mx0, __shfl_xor_sync(0xffffffffu, mx0, 1));
        mx0 = fmaxf(mx0, __shfl_xor_sync(0xffffffffu, mx0, 2));
        mx1 = fmaxf(mx1, __shfl_xor_sync(0xffffffffu, mx1, 1));
        mx1 = fmaxf(mx1, __shfl_xor_sync(0xffffffffu, mx1, 2));
        float mn0 = fmaxf(m0, mx0), mn1 = fmaxf(m1, mx1);
        float al0 = __expf(m0 - mn0), al1 = __expf(m1 - mn1);
        float ls0 = 0.f, ls1 = 0.f;
#pragma unroll
        for (int n = 0; n < 8; n++) {
            sf[n][0] = __expf(sf[n][0] - mn0); ls0 += sf[n][0];
            sf[n][1] = __expf(sf[n][1] - mn0); ls0 += sf[n][1];
            sf[n][2] = __expf(sf[n][2] - mn1); ls1 += sf[n][2];
            sf[n][3] = __expf(sf[n][3] - mn1); ls1 += sf[n][3];
        }
        ls0 += __shfl_xor_sync(0xffffffffu, ls0, 1);
        ls0 += __shfl_xor_sync(0xffffffffu, ls0, 2);
        ls1 += __shfl_xor_sync(0xffffffffu, ls1, 1);
        ls1 += __shfl_xor_sync(0xffffffffu, ls1, 2);
        l0 = l0 * al0 + ls0; m0 = mn0;
        l1 = l1 * al1 + ls1; m1 = mn1;
#pragma unroll
        for (int n = 0; n < 8; n++) {
            o[n][0] *= al0; o[n][1] *= al0; o[n][2] *= al1; o[n][3] *= al1;
        }

#pragma unroll
        for (int j = 0; j < 4; j++) {
            float p00 = sf[2 * j][0], p01 = sf[2 * j][1];
            float p10 = sf[2 * j][2], p11 = sf[2 * j][3];
            float p20 = sf[2 * j + 1][0], p21 = sf[2 * j + 1][1];
            float p30 = sf[2 * j + 1][2], p31 = sf[2 * j + 1][3];
            uint32_t ahp[4], alp[4];
            ahp[0] = pack_bf16x2(p00, p01);
            ahp[1] = pack_bf16x2(p10, p11);
            ahp[2] = pack_bf16x2(p20, p21);
            ahp[3] = pack_bf16x2(p30, p31);
            alp[0] = pack_bf16x2(p00 - __bfloat162float(__float2bfloat16(p00)),
                                 p01 - __bfloat162float(__float2bfloat16(p01)));
            alp[1] = pack_bf16x2(p10 - __bfloat162float(__float2bfloat16(p10)),
                                 p11 - __bfloat162float(__float2bfloat16(p11)));
            alp[2] = pack_bf16x2(p20 - __bfloat162float(__float2bfloat16(p20)),
                                 p21 - __bfloat162float(__float2bfloat16(p21)));
            alp[3] = pack_bf16x2(p30 - __bfloat162float(__float2bfloat16(p30)),
                                 p31 - __bfloat162float(__float2bfloat16(p31)));
#pragma unroll
            for (int n = 0; n < 8; n++) {
                uint2 bh2 = *(const uint2*)(smraw + soff + FOFF_VHI + ((j * 8 + n) * 32 + lane) * 8);
                uint2 bl2 = *(const uint2*)(smraw + soff + FOFF_VLO + ((j * 8 + n) * 32 + lane) * 8);
                uint32_t bh[2] = {bh2.x, bh2.y};
                uint32_t bl[2] = {bl2.x, bl2.y};
                mma_bf16(o[n], ahp, bh);
                mma_bf16(o[n], alp, bh);
                mma_bf16(o[n], ahp, bl);
            }
        }
    }

    float inv0 = 1.f / l0, inv1 = 1.f / l1;
    float* Og = g_ab + (size_t)(b * SQ + qt * 128 + wid * 16) * DM + h * HD;
#pragma unroll
    for (int n = 0; n < 8; n++) {
        int c = n * 8 + 2 * tig;
        *(float2*)(Og + (size_t)g * DM + c) = make_float2(o[n][0] * inv0, o[n][1] * inv0);
        *(float2*)(Og + (size_t)(g + 8) * DM + c) = make_float2(o[n][2] * inv1, o[n][3] * inv1);
    }
}

// ================= launcher =================
extern "C" void kernel_launch(void* const* d_in, const int* in_sizes, int n_in,
                              void* d_out, int out_size) {
    (void)in_sizes; (void)n_in; (void)out_size;
    const float* query = (const float*)d_in[0];
    const float* key   = (const float*)d_in[1];
    const float* value = (const float*)d_in[2];
    const float* wq    = (const float*)d_in[3];
    const float* wk    = (const float*)d_in[4];
    const float* wv    = (const float*)d_in[5];
    const float* wo    = (const float*)d_in[6];
    float* out = (float*)d_out;

    const int smem_gemm  = 65536;               // 2 stages x (16KB A + 16KB W)
    const int smem_flash = 65536 + 2 * 49152;   // 160KB
    cudaFuncSetAttribute(gemm_qkv,   cudaFuncAttributeMaxDynamicSharedMemorySize, smem_gemm);
    cudaFuncSetAttribute(gemm_out,   cudaFuncAttributeMaxDynamicSharedMemorySize, smem_gemm);
    cudaFuncSetAttribute(flash_mma2, cudaFuncAttributeMaxDynamicSharedMemorySize, smem_flash);

    const int nf4 = MTOT * DM / 4;   // 1048576 float4s -> 4096 blocks of 256

    prep_k<<<dim3(nf4 / 256, 4), 256>>>(query, key, value, wq, wk, wv, wo);  // 1
    ternarize_k<<<(4 * DM * DM) / 256, 256>>>(wq, wk, wv, wo);               // 2
    gemm_qkv<<<dim3(DM / 128, MTOT / 128, 3), 256, smem_gemm>>>();           // 3
    frag_writer<<<dim3(32, 16, 6), 256>>>();                                 // 4 <- profiled
    flash_mma2<<<dim3(SQ / 128, NH, NB), 256, smem_flash>>>();               // 5
    quant2_k<<<nf4 / 256, 256>>>();                                          // 6
    gemm_out<<<dim3(DM / 128, MTOT / 128), 256, smem_gemm>>>(out);           // 7
}

// round 12
// speedup vs baseline: 1.5812x; 1.5812x over previous
#include <cuda_runtime.h>
#include <cuda_bf16.h>
#include <cstdint>
#include <math.h>

#define DM 1024
#define NH 16
#define HD 64
#define NB 2
#define SQ 2048
#define MTOT (NB*SQ)   // 4096

// ================= mma.sync helpers =================
__device__ __forceinline__ uint32_t smem_u32(const void* p) {
    uint32_t a;
    asm("{ .reg .u64 t; cvta.to.shared.u64 t, %1; cvt.u32.u64 %0, t; }" : "=r"(a) : "l"(p));
    return a;
}
__device__ __forceinline__ void ldm_x4(uint32_t* r, uint32_t addr) {
    asm volatile("ldmatrix.sync.aligned.m8n8.x4.shared.b16 {%0,%1,%2,%3}, [%4];"
                 : "=r"(r[0]), "=r"(r[1]), "=r"(r[2]), "=r"(r[3]) : "r"(addr));
}
__device__ __forceinline__ void mma_bf16(float* d, const uint32_t* a, const uint32_t* b) {
    asm volatile("mma.sync.aligned.m16n8k16.row.col.f32.bf16.bf16.f32 "
                 "{%0,%1,%2,%3}, {%4,%5,%6,%7}, {%8,%9}, {%0,%1,%2,%3};"
                 : "+f"(d[0]), "+f"(d[1]), "+f"(d[2]), "+f"(d[3])
                 : "r"(a[0]), "r"(a[1]), "r"(a[2]), "r"(a[3]), "r"(b[0]), "r"(b[1]));
}
__device__ __forceinline__ void mma_tf32(float* d, const uint32_t* a, const uint32_t* b) {
    asm volatile("mma.sync.aligned.m16n8k8.row.col.f32.tf32.tf32.f32 "
                 "{%0,%1,%2,%3}, {%4,%5,%6,%7}, {%8,%9}, {%0,%1,%2,%3};"
                 : "+f"(d[0]), "+f"(d[1]), "+f"(d[2]), "+f"(d[3])
                 : "r"(a[0]), "r"(a[1]), "r"(a[2]), "r"(a[3]), "r"(b[0]), "r"(b[1]));
}
__device__ __forceinline__ uint32_t cvt_tf32(float x) {
    uint32_t r; asm("cvt.rna.tf32.f32 %0, %1;" : "=r"(r) : "f"(x)); return r;
}
__device__ __forceinline__ void cp_async16(uint32_t saddr, const void* gaddr) {
    asm volatile("cp.async.cg.shared.global [%0], [%1], 16;" :: "r"(saddr), "l"(gaddr));
}
#define CP_COMMIT() asm volatile("cp.async.commit_group;")
#define CP_WAIT1()  asm volatile("cp.async.wait_group 1;")
#define CP_WAIT0()  asm volatile("cp.async.wait_group 0;")
#define SW128(off) ((off) ^ (((off) >> 3) & 0x70))
__device__ __forceinline__ uint32_t pack_bf16x2(float x, float y) {
    __nv_bfloat162 t = __floats2bfloat162_rn(x, y);
    return *(uint32_t*)&t;
}

// ================= scratch =================
__device__ __nv_bfloat16 g_twb[4][DM*DM];    // ternary weights bf16 {-1,0,1}
__device__ __nv_bfloat16 g_sq[MTOT*3*DM];    // 3-limb split of query (reused for out-proj input)
__device__ __nv_bfloat16 g_sk[MTOT*3*DM];    // 3-limb split of key
__device__ __nv_bfloat16 g_sv[MTOT*2*DM];    // 2-limb split of value
__device__ float  g_qb[MTOT*DM];
__device__ float  g_kb[MTOT*DM];
__device__ float  g_vb[MTOT*DM];
__device__ float  g_ab[MTOT*DM];
__device__ double g_part[4][32];
// fragment-layout operands for flash attention
__device__ uint32_t g_qfhi[512*8192];   // [(b*16+qt)*16+h] tiles: [ks8][w8][lane32][r4]
__device__ uint32_t g_qflo[512*8192];
__device__ uint32_t g_kfhi[1024*4096];  // [(b*16+h)*32+kt] tiles: [ks8][n8][lane32][r2]
__device__ uint32_t g_kflo[1024*4096];
__device__ uint32_t g_vfhi[1024*2048];  // [(b*16+h)*32+kt] tiles: [j4][n8][lane32][r2]
__device__ uint32_t g_vflo[1024*2048];

// ================= abs-mean + ternarize (final reduction folded in) =================
__global__ void absmean_partial(const float* __restrict__ w0, const float* __restrict__ w1,
                                const float* __restrict__ w2, const float* __restrict__ w3) {
    int mid = blockIdx.x >> 5, blk = blockIdx.x & 31;
    const float* w = (mid == 0) ? w0 : (mid == 1) ? w1 : (mid == 2) ? w2 : w3;
    const int chunk = (DM * DM) / 32;
    const float* p = w + blk * chunk;
    double acc = 0.0;
    for (int i = threadIdx.x; i < chunk; i += blockDim.x) acc += (double)fabsf(p[i]);
    __shared__ double sred[256];
    sred[threadIdx.x] = acc;
    __syncthreads();
    for (int s = 128; s > 0; s >>= 1) {
        if (threadIdx.x < s) sred[threadIdx.x] += sred[threadIdx.x + s];
        __syncthreads();
    }
    if (threadIdx.x == 0) g_part[mid][blk] = sred[0];
}
__global__ void ternarize_k(const float* __restrict__ w0, const float* __restrict__ w1,
                            const float* __restrict__ w2, const float* __restrict__ w3) {
    int idx = blockIdx.x * blockDim.x + threadIdx.x;
    int mid = idx >> 20, off = idx & ((1 << 20) - 1);
    const float* w = (mid == 0) ? w0 : (mid == 1) ? w1 : (mid == 2) ? w2 : w3;
    __shared__ float s_thr;
    if (threadIdx.x == 0) {
        double s = 0.0;
#pragma unroll
        for (int i = 0; i < 32; i++) s += g_part[mid][i];
        s_thr = (float)(s / (double)(DM * DM));
    }
    __syncthreads();
    float t = s_thr;
    float x = w[off];
    float v = (fabsf(x) > t) ? (x > 0.f ? 1.f : -1.f) : 0.f;
    g_twb[mid][off] = __float2bfloat16(v);
}

// ================= combined input limb splits =================
__device__ __forceinline__ void store_bf4(__nv_bfloat16* dst, float a, float b, float c, float d) {
    __nv_bfloat162* p = (__nv_bfloat162*)dst;
    p[0] = __floats2bfloat162_rn(a, b);
    p[1] = __floats2bfloat162_rn(c, d);
}
__global__ void split_all(const float* __restrict__ Q, const float* __restrict__ K,
                          const float* __restrict__ V) {
    const int z = blockIdx.y;
    const float* X = (z == 0) ? Q : (z == 1) ? K : V;
    int i = blockIdx.x * blockDim.x + threadIdx.x;
    int m = i >> 8, j = (i & 255) * 4;
    float4 x = ((const float4*)X)[i];
    float h0 = __bfloat162float(__float2bfloat16(x.x));
    float h1 = __bfloat162float(__float2bfloat16(x.y));
    float h2 = __bfloat162float(__float2bfloat16(x.z));
    float h3 = __bfloat162float(__float2bfloat16(x.w));
    float r0 = x.x - h0, r1 = x.y - h1, r2 = x.z - h2, r3 = x.w - h3;
    if (z == 2) {
        __nv_bfloat16* base = g_sv + (size_t)m * 2048;
        store_bf4(base + j, h0, h1, h2, h3);
        store_bf4(base + 1024 + j, r0, r1, r2, r3);
    } else {
        float m0 = __bfloat162float(__float2bfloat16(r0));
        float m1 = __bfloat162float(__float2bfloat16(r1));
        float m2 = __bfloat162float(__float2bfloat16(r2));
        float m3 = __bfloat162float(__float2bfloat16(r3));
        __nv_bfloat16* base = ((z == 0) ? g_sq : g_sk) + (size_t)m * 3072;
        store_bf4(base + j, h0, h1, h2, h3);
        store_bf4(base + 1024 + j, m0, m1, m2, m3);
        store_bf4(base + 2048 + j, r0 - m0, r1 - m1, r2 - m2, r3 - m3);
    }
}
// out-proj input split (2 limbs of g_ab -> g_sq)
__global__ void split2_k() {
    int i = blockIdx.x * blockDim.x + threadIdx.x;
    int m = i >> 8, j = (i & 255) * 4;
    float4 x = ((const float4*)g_ab)[i];
    float h0 = __bfloat162float(__float2bfloat16(x.x));
    float h1 = __bfloat162float(__float2bfloat16(x.y));
    float h2 = __bfloat162float(__float2bfloat16(x.z));
    float h3 = __bfloat162float(__float2bfloat16(x.w));
    __nv_bfloat16* base = g_sq + (size_t)m * 2048;
    store_bf4(base + j, h0, h1, h2, h3);
    store_bf4(base + 1024 + j, x.x - h0, x.y - h1, x.z - h2, x.w - h3);
}

// ================= GEMM mainloop: bf16 HMMA, BK = 128 elements per stage ============
// Stage (64KB) = A: 2 x 16KB SW128 sub-chunks (k 0-63, 64-127) + B: same. 2 stages = 128KB.
// Halves the number of sync/wait boundaries per unit tensor work vs BK=64.
__device__ __forceinline__ void gemm_body(const __nv_bfloat16* __restrict__ A,
                                          const __nv_bfloat16* __restrict__ W,
                                          float* __restrict__ C,
                                          int KA, char* smraw) {
    const int tid = threadIdx.x, lane = tid & 31, wid = tid >> 5;
    const int wm = (wid >> 2) * 64, wn = (wid & 3) * 32;
    const int row0 = blockIdx.y * 128, col0 = blockIdx.x * 128;
    const uint32_t sbase = smem_u32(smraw);

    float acc[4][4][4];
#pragma unroll
    for (int i = 0; i < 4; i++)
#pragma unroll
        for (int j = 0; j < 4; j++)
#pragma unroll
            for (int k = 0; k < 4; k++) acc[i][j][k] = 0.f;

    const int NIT = KA >> 7;   // BK = 128 elements

#pragma unroll 1
    for (int pre = 0; pre < 2; pre++) {
        const int k0 = pre * 128;
        const uint32_t st = sbase + pre * 65536u;
#pragma unroll
        for (int sub = 0; sub < 2; sub++) {
            const uint32_t sa = st + sub * 16384u;
            const uint32_t sb = st + 32768u + sub * 16384u;
            const int ke = k0 + sub * 64;
#pragma unroll
            for (int j = 0; j < 4; j++) {
                int c = tid * 4 + j;
                int r = c >> 3, g = c & 7;
                cp_async16(sa + SW128(r * 128 + g * 16), A + (size_t)(row0 + r) * KA + ke + g * 8);
                cp_async16(sb + SW128(r * 128 + g * 16), W + (size_t)(col0 + r) * 1024 + (ke & 1023) + g * 8);
            }
        }
        CP_COMMIT();
    }

    for (int it = 0; it < NIT; it++) {
        CP_WAIT1();
        __syncthreads();
        const uint32_t st = sbase + (it & 1) * 65536u;
#pragma unroll
        for (int ks = 0; ks < 8; ks++) {
            const uint32_t sa = st + (ks >> 2) * 16384u;
            const uint32_t sb = st + 32768u + (ks >> 2) * 16384u;
            const int ksl = ks & 3;
            uint32_t a[4][4];
#pragma unroll
            for (int mi = 0; mi < 4; mi++)
                ldm_x4(a[mi], sa + SW128((wm + mi * 16 + (lane & 15)) * 128 +
                                         (2 * ksl + (lane >> 4)) * 16));
            uint32_t b[2][4];
#pragma unroll
            for (int p = 0; p < 2; p++)
                ldm_x4(b[p], sb + SW128((wn + p * 16 + ((lane >> 4) << 3) + (lane & 7)) * 128 +
                                        (2 * ksl + ((lane >> 3) & 1)) * 16));
#pragma unroll
            for (int mi = 0; mi < 4; mi++)
#pragma unroll
                for (int ni = 0; ni < 4; ni++)
                    mma_bf16(acc[mi][ni], a[mi], &b[ni >> 1][(ni & 1) * 2]);
        }
        __syncthreads();
        if (it + 2 < NIT) {
            const int k0 = (it + 2) * 128;
            const uint32_t st2 = sbase + ((it + 2) & 1) * 65536u;
#pragma unroll
            for (int sub = 0; sub < 2; sub++) {
                const uint32_t sa2 = st2 + sub * 16384u;
                const uint32_t sb2 = st2 + 32768u + sub * 16384u;
                const int ke = k0 + sub * 64;
#pragma unroll
                for (int j = 0; j < 4; j++) {
                    int c = tid * 4 + j;
                    int r = c >> 3, g = c & 7;
                    cp_async16(sa2 + SW128(r * 128 + g * 16), A + (size_t)(row0 + r) * KA + ke + g * 8);
                    cp_async16(sb2 + SW128(r * 128 + g * 16), W + (size_t)(col0 + r) * 1024 + (ke & 1023) + g * 8);
                }
            }
            CP_COMMIT();
        }
    }

#pragma unroll
    for (int mi = 0; mi < 4; mi++)
#pragma unroll
        for (int ni = 0; ni < 4; ni++) {
            int r = row0 + wm + mi * 16 + (lane >> 2);
            int c = col0 + wn + ni * 8 + 2 * (lane & 3);
            *(float2*)&C[(size_t)r * DM + c] = make_float2(acc[mi][ni][0], acc[mi][ni][1]);
            *(float2*)&C[(size_t)(r + 8) * DM + c] = make_float2(acc[mi][ni][2], acc[mi][ni][3]);
        }
}

// mega GEMM: z=0 q (KA=3072 -> g_qb), z=1 k (3072 -> g_kb), z=2 v (2048 -> g_vb)
__global__ __launch_bounds__(256, 1) void gemm_qkv() {
    extern __shared__ char smraw[];
    const int z = blockIdx.z;
    const __nv_bfloat16* A = (z == 0) ? g_sq : (z == 1) ? g_sk : g_sv;
    float* C = (z == 0) ? g_qb : (z == 1) ? g_kb : g_vb;
    gemm_body(A, g_twb[z], C, (z == 2) ? 2048 : 3072, smraw);
}
// output projection GEMM (KA=2048, A=g_sq, C=out)
__global__ __launch_bounds__(256, 1) void gemm_out(float* __restrict__ out) {
    extern __shared__ char smraw[];
    gemm_body(g_sq, g_twb[3], out, 2048, smraw);
}

// ================= merged fragment writer =================
// grid (32, 16, 6): z = kind*2 + b, kind 0=Q (x<16), 1=K, 2=V; y = head
__global__ __launch_bounds__(256) void frag_writer() {
    __shared__ float tile[128 * 65];
    const int kind = blockIdx.z >> 1, b = blockIdx.z & 1;
    const int h = blockIdx.y;
    const int tid = threadIdx.x;

    if (kind == 0) {
        const int qt = blockIdx.x;
        if (qt >= 16) return;
        for (int idx = tid; idx < 128 * 64; idx += 256) {
            int row = idx >> 6, col = idx & 63;
            tile[row * 65 + col] = g_qb[(size_t)(b * SQ + qt * 128 + row) * DM + h * HD + col];
        }
        __syncthreads();
        size_t base = (size_t)((b * 16 + qt) * 16 + h) * 8192;
        for (int t2 = tid; t2 < 8192; t2 += 256) {
            int r = t2 & 3, lane = (t2 >> 2) & 31, w = (t2 >> 7) & 7, ks = (t2 >> 10) & 7;
            int g = lane >> 2, tig = lane & 3;
            int row = w * 16 + g + 8 * (r & 1);
            int col = ks * 8 + tig + 4 * (r >> 1);
            float v = tile[row * 65 + col] * 0.125f;
            uint32_t hi = cvt_tf32(v);
            g_qfhi[base + t2] = hi;
            g_qflo[base + t2] = cvt_tf32(v - __uint_as_float(hi));
        }
    } else if (kind == 1) {
        const int kt = blockIdx.x;
        for (int idx = tid; idx < 64 * 64; idx += 256) {
            int row = idx >> 6, col = idx & 63;
            tile[row * 65 + col] = g_kb[(size_t)(b * SQ + kt * 64 + row) * DM + h * HD + col];
        }
        __syncthreads();
        size_t base = (size_t)((b * 16 + h) * 32 + kt) * 4096;
        for (int t2 = tid; t2 < 4096; t2 += 256) {
            int r = t2 & 1, lane = (t2 >> 1) & 31, n = (t2 >> 6) & 7, ks = (t2 >> 9) & 7;
            int g = lane >> 2, tig = lane & 3;
            int key = n * 8 + g;
            int d = ks * 8 + tig + 4 * r;
            float v = tile[key * 65 + d];
            uint32_t hi = cvt_tf32(v);
            g_kfhi[base + t2] = hi;
            g_kflo[base + t2] = cvt_tf32(v - __uint_as_float(hi));
        }
    } else {
        const int kt = blockIdx.x;
        for (int idx = tid; idx < 64 * 64; idx += 256) {
            int row = idx >> 6, col = idx & 63;
            tile[row * 65 + col] = g_vb[(size_t)(b * SQ + kt * 64 + row) * DM + h * HD + col];
        }
        __syncthreads();
        size_t base = (size_t)((b * 16 + h) * 32 + kt) * 2048;
        for (int t2 = tid; t2 < 2048; t2 += 256) {
            int r = t2 & 1, lane = (t2 >> 1) & 31, n = (t2 >> 6) & 7, j = (t2 >> 9) & 3;
            int g = lane >> 2, tig = lane & 3;
            int key0 = j * 16 + 2 * tig + 8 * r;
            int d = n * 8 + g;
            float v0 = tile[key0 * 65 + d];
            float v1 = tile[(key0 + 1) * 65 + d];
            float h0 = __bfloat162float(__float2bfloat16(v0));
            float h1 = __bfloat162float(__float2bfloat16(v1));
            g_vfhi[base + t2] = pack_bf16x2(v0, v1);
            g_vflo[base + t2] = pack_bf16x2(v0 - h0, v1 - h1);
        }
    }
}

// ================= flash attention (R6-proven, unchanged) ======================
#define FOFF_QHI 0u
#define FOFF_QLO 32768u
#define FOFF_ST  65536u
#define FSTAGE   49152u
#define FOFF_KHI 0u
#define FOFF_KLO 16384u
#define FOFF_VHI 32768u
#define FOFF_VLO 40960u
__global__ __launch_bounds__(256) void flash_mma2() {
    extern __shared__ char smraw[];
    const uint32_t sbase = smem_u32(smraw);
    const int qt = blockIdx.x, h = blockIdx.y, b = blockIdx.z;
    const int tid = threadIdx.x, lane = tid & 31, wid = tid >> 5;
    const int g = lane >> 2, tig = lane & 3;

    const uint32_t* Qhi = g_qfhi + (size_t)((b * 16 + qt) * 16 + h) * 8192;
    const uint32_t* Qlo = g_qflo + (size_t)((b * 16 + qt) * 16 + h) * 8192;
    const uint32_t* Khi = g_kfhi + (size_t)((b * 16 + h) * 32) * 4096;
    const uint32_t* Klo = g_kflo + (size_t)((b * 16 + h) * 32) * 4096;
    const uint32_t* Vhi = g_vfhi + (size_t)((b * 16 + h) * 32) * 2048;
    const uint32_t* Vlo = g_vflo + (size_t)((b * 16 + h) * 32) * 2048;

#pragma unroll
    for (int i = 0; i < 8; i++) {
        int idx = tid + i * 256;
        cp_async16(sbase + FOFF_QHI + idx * 16, Qhi + idx * 4);
        cp_async16(sbase + FOFF_QLO + idx * 16, Qlo + idx * 4);
    }
    CP_COMMIT();

    {
        const uint32_t st = sbase + FOFF_ST;
#pragma unroll
        for (int i = 0; i < 4; i++) {
            int idx = tid + i * 256;
            cp_async16(st + FOFF_KHI + idx * 16, Khi + idx * 4);
            cp_async16(st + FOFF_KLO + idx * 16, Klo + idx * 4);
        }
#pragma unroll
        for (int i = 0; i < 2; i++) {
            int idx = tid + i * 256;
            cp_async16(st + FOFF_VHI + idx * 16, Vhi + idx * 4);
            cp_async16(st + FOFF_VLO + idx * 16, Vlo + idx * 4);
        }
        CP_COMMIT();
    }

    float o[8][4];
#pragma unroll
    for (int n = 0; n < 8; n++)
#pragma unroll
        for (int k = 0; k < 4; k++) o[n][k] = 0.f;
    float m0 = -1e30f, m1 = -1e30f, l0 = 0.f, l1 = 0.f;

    for (int t = 0; t < 32; t++) {
        CP_WAIT0();
        __syncthreads();
        if (t + 1 < 32) {
            const uint32_t st = sbase + FOFF_ST + ((t + 1) & 1) * FSTAGE;
            const uint32_t* kh = Khi + (size_t)(t + 1) * 4096;
            const uint32_t* kl = Klo + (size_t)(t + 1) * 4096;
            const uint32_t* vh = Vhi + (size_t)(t + 1) * 2048;
            const uint32_t* vl = Vlo + (size_t)(t + 1) * 2048;
#pragma unroll
            for (int i = 0; i < 4; i++) {
                int idx = tid + i * 256;
                cp_async16(st + FOFF_KHI + idx * 16, kh + idx * 4);
                cp_async16(st + FOFF_KLO + idx * 16, kl + idx * 4);
            }
#pragma unroll
            for (int i = 0; i < 2; i++) {
                int idx = tid + i * 256;
                cp_async16(st + FOFF_VHI + idx * 16, vh + idx * 4);
                cp_async16(st + FOFF_VLO + idx * 16, vl + idx * 4);
            }
            CP_COMMIT();
        }
        const uint32_t soff = FOFF_ST + (t & 1) * FSTAGE;

        float sf[8][4];
#pragma unroll
        for (int n = 0; n < 8; n++)
#pragma unroll
            for (int k = 0; k < 4; k++) sf[n][k] = 0.f;
#pragma unroll
        for (int ks = 0; ks < 8; ks++) {
            uint4 qa = *(const uint4*)(smraw + FOFF_QHI + ((ks * 8 + wid) * 32 + lane) * 16);
            uint4 ql = *(const uint4*)(smraw + FOFF_QLO + ((ks * 8 + wid) * 32 + lane) * 16);
            uint32_t ah[4] = {qa.x, qa.y, qa.z, qa.w};
            uint32_t al[4] = {ql.x, ql.y, ql.z, ql.w};
#pragma unroll
            for (int n = 0; n < 8; n++) {
                uint2 bh2 = *(const uint2*)(smraw + soff + FOFF_KHI + ((ks * 8 + n) * 32 + lane) * 8);
                uint2 bl2 = *(const uint2*)(smraw + soff + FOFF_KLO + ((ks * 8 + n) * 32 + lane) * 8);
                uint32_t bh[2] = {bh2.x, bh2.y};
                uint32_t bl[2] = {bl2.x, bl2.y};
                mma_tf32(sf[n], ah, bh);
                mma_tf32(sf[n], ah, bl);
                mma_tf32(sf[n], al, bh);
            }
        }

        float mx0 = -1e30f, mx1 = -1e30f;
#pragma unroll
        for (int n = 0; n < 8; n++) {
            mx0 = fmaxf(mx0, fmaxf(sf[n][0], sf[n][1]));
            mx1 = fmaxf(mx1, fmaxf(sf[n][2], sf[n][3]));
        }
        mx0 = fmaxf(mx0, __shfl_xor_sync(0xffffffffu, mx0, 1));
        mx0 = fmaxf(mx0, __shfl_xor_sync(0xffffffffu, mx0, 2));
        mx1 = fmaxf(mx1, __shfl_xor_sync(0xffffffffu, mx1, 1));
        mx1 = fmaxf(mx1, __shfl_xor_sync(0xffffffffu, mx1, 2));
        float mn0 = fmaxf(m0, mx0), mn1 = fmaxf(m1, mx1);
        float al0 = __expf(m0 - mn0), al1 = __expf(m1 - mn1);
        float ls0 = 0.f, ls1 = 0.f;
#pragma unroll
        for (int n = 0; n < 8; n++) {
            sf[n][0] = __expf(sf[n][0] - mn0); ls0 += sf[n][0];
            sf[n][1] = __expf(sf[n][1] - mn0); ls0 += sf[n][1];
            sf[n][2] = __expf(sf[n][2] - mn1); ls1 += sf[n][2];
            sf[n][3] = __expf(sf[n][3] - mn1); ls1 += sf[n][3];
        }
        ls0 += __shfl_xor_sync(0xffffffffu, ls0, 1);
        ls0 += __shfl_xor_sync(0xffffffffu, ls0, 2);
        ls1 += __shfl_xor_sync(0xffffffffu, ls1, 1);
        ls1 += __shfl_xor_sync(0xffffffffu, ls1, 2);
        l0 = l0 * al0 + ls0; m0 = mn0;
        l1 = l1 * al1 + ls1; m1 = mn1;
#pragma unroll
        for (int n = 0; n < 8; n++) {
            o[n][0] *= al0; o[n][1] *= al0; o[n][2] *= al1; o[n][3] *= al1;
        }

#pragma unroll
        for (int j = 0; j < 4; j++) {
            float p00 = sf[2 * j][0], p01 = sf[2 * j][1];
            float p10 = sf[2 * j][2], p11 = sf[2 * j][3];
            float p20 = sf[2 * j + 1][0], p21 = sf[2 * j + 1][1];
            float p30 = sf[2 * j + 1][2], p31 = sf[2 * j + 1][3];
            uint32_t ahp[4], alp[4];
            ahp[0] = pack_bf16x2(p00, p01);
            ahp[1] = pack_bf16x2(p10, p11);
            ahp[2] = pack_bf16x2(p20, p21);
            ahp[3] = pack_bf16x2(p30, p31);
            alp[0] = pack_bf16x2(p00 - __bfloat162float(__float2bfloat16(p00)),
                                 p01 - __bfloat162float(__float2bfloat16(p01)));
            alp[1] = pack_bf16x2(p10 - __bfloat162float(__float2bfloat16(p10)),
                                 p11 - __bfloat162float(__float2bfloat16(p11)));
            alp[2] = pack_bf16x2(p20 - __bfloat162float(__float2bfloat16(p20)),
                                 p21 - __bfloat162float(__float2bfloat16(p21)));
            alp[3] = pack_bf16x2(p30 - __bfloat162float(__float2bfloat16(p30)),
                                 p31 - __bfloat162float(__float2bfloat16(p31)));
#pragma unroll
            for (int n = 0; n < 8; n++) {
                uint2 bh2 = *(const uint2*)(smraw + soff + FOFF_VHI + ((j * 8 + n) * 32 + lane) * 8);
                uint2 bl2 = *(const uint2*)(smraw + soff + FOFF_VLO + ((j * 8 + n) * 32 + lane) * 8);
                uint32_t bh[2] = {bh2.x, bh2.y};
                uint32_t bl[2] = {bl2.x, bl2.y};
                mma_bf16(o[n], ahp, bh);
                mma_bf16(o[n], alp, bh);
                mma_bf16(o[n], ahp, bl);
            }
        }
    }

    float inv0 = 1.f / l0, inv1 = 1.f / l1;
    float* Og = g_ab + (size_t)(b * SQ + qt * 128 + wid * 16) * DM + h * HD;
#pragma unroll
    for (int n = 0; n < 8; n++) {
        int c = n * 8 + 2 * tig;
        *(float2*)(Og + (size_t)g * DM + c) = make_float2(o[n][0] * inv0, o[n][1] * inv0);
        *(float2*)(Og + (size_t)(g + 8) * DM + c) = make_float2(o[n][2] * inv1, o[n][3] * inv1);
    }
}

// ================= launcher =================
extern "C" void kernel_launch(void* const* d_in, const int* in_sizes, int n_in,
                              void* d_out, int out_size) {
    (void)in_sizes; (void)n_in; (void)out_size;
    const float* query = (const float*)d_in[0];
    const float* key   = (const float*)d_in[1];
    const float* value = (const float*)d_in[2];
    const float* wq    = (const float*)d_in[3];
    const float* wk    = (const float*)d_in[4];
    const float* wv    = (const float*)d_in[5];
    const float* wo    = (const float*)d_in[6];
    float* out = (float*)d_out;

    const int smem_gemm  = 131072;              // 2 stages x 64KB (BK=128)
    const int smem_flash = 65536 + 2 * 49152;   // 160KB
    cudaFuncSetAttribute(gemm_qkv,   cudaFuncAttributeMaxDynamicSharedMemorySize, smem_gemm);
    cudaFuncSetAttribute(gemm_out,   cudaFuncAttributeMaxDynamicSharedMemorySize, smem_gemm);
    cudaFuncSetAttribute(flash_mma2, cudaFuncAttributeMaxDynamicSharedMemorySize, smem_flash);

    const int nf4 = MTOT * DM / 4;

    absmean_partial<<<128, 256>>>(wq, wk, wv, wo);                    // 1
    ternarize_k<<<(4 * DM * DM) / 256, 256>>>(wq, wk, wv, wo);        // 2
    split_all<<<dim3(nf4 / 256, 3), 256>>>(query, key, value);        // 3
    gemm_qkv<<<dim3(DM / 128, MTOT / 128, 3), 256, smem_gemm>>>();    // 4  <- profiled
    frag_writer<<<dim3(32, 16, 6), 256>>>();                          // 5
    flash_mma2<<<dim3(SQ / 128, NH, NB), 256, smem_flash>>>();        // 6
    split2_k<<<nf4 / 256, 256>>>();                                   // 7
    gemm_out<<<dim3(DM / 128, MTOT / 128), 256, smem_gemm>>>(out);    // 8
}

// round 14
// speedup vs baseline: 1.7230x; 1.0897x over previous
#include <cuda_runtime.h>
#include <cuda_bf16.h>
#include <cstdint>
#include <math.h>

#define DM 1024
#define NH 16
#define HD 64
#define NB 2
#define SQ 2048
#define MTOT (NB*SQ)   // 4096

// ================= mma.sync helpers =================
__device__ __forceinline__ uint32_t smem_u32(const void* p) {
    uint32_t a;
    asm("{ .reg .u64 t; cvta.to.shared.u64 t, %1; cvt.u32.u64 %0, t; }" : "=r"(a) : "l"(p));
    return a;
}
__device__ __forceinline__ void ldm_x4(uint32_t* r, uint32_t addr) {
    asm volatile("ldmatrix.sync.aligned.m8n8.x4.shared.b16 {%0,%1,%2,%3}, [%4];"
                 : "=r"(r[0]), "=r"(r[1]), "=r"(r[2]), "=r"(r[3]) : "r"(addr));
}
__device__ __forceinline__ void mma_bf16(float* d, const uint32_t* a, const uint32_t* b) {
    asm volatile("mma.sync.aligned.m16n8k16.row.col.f32.bf16.bf16.f32 "
                 "{%0,%1,%2,%3}, {%4,%5,%6,%7}, {%8,%9}, {%0,%1,%2,%3};"
                 : "+f"(d[0]), "+f"(d[1]), "+f"(d[2]), "+f"(d[3])
                 : "r"(a[0]), "r"(a[1]), "r"(a[2]), "r"(a[3]), "r"(b[0]), "r"(b[1]));
}
__device__ __forceinline__ void mma_tf32(float* d, const uint32_t* a, const uint32_t* b) {
    asm volatile("mma.sync.aligned.m16n8k8.row.col.f32.tf32.tf32.f32 "
                 "{%0,%1,%2,%3}, {%4,%5,%6,%7}, {%8,%9}, {%0,%1,%2,%3};"
                 : "+f"(d[0]), "+f"(d[1]), "+f"(d[2]), "+f"(d[3])
                 : "r"(a[0]), "r"(a[1]), "r"(a[2]), "r"(a[3]), "r"(b[0]), "r"(b[1]));
}
__device__ __forceinline__ uint32_t cvt_tf32(float x) {
    uint32_t r; asm("cvt.rna.tf32.f32 %0, %1;" : "=r"(r) : "f"(x)); return r;
}
__device__ __forceinline__ void cp_async16(uint32_t saddr, const void* gaddr) {
    asm volatile("cp.async.cg.shared.global [%0], [%1], 16;" :: "r"(saddr), "l"(gaddr));
}
#define CP_COMMIT() asm volatile("cp.async.commit_group;")
#define CP_WAIT1()  asm volatile("cp.async.wait_group 1;")
#define CP_WAIT0()  asm volatile("cp.async.wait_group 0;")
#define SW128(off) ((off) ^ (((off) >> 3) & 0x70))
__device__ __forceinline__ uint32_t pack_bf16x2(float x, float y) {
    __nv_bfloat162 t = __floats2bfloat162_rn(x, y);
    return *(uint32_t*)&t;
}

// ================= scratch =================
__device__ __nv_bfloat16 g_twb[4][DM*DM];    // ternary weights bf16 {-1,0,1}
__device__ __nv_bfloat16 g_sq[MTOT*3*DM];    // 3-limb split of query (reused: out-proj input limbs)
__device__ __nv_bfloat16 g_sk[MTOT*3*DM];    // 3-limb split of key
__device__ __nv_bfloat16 g_sv[MTOT*2*DM];    // 2-limb split of value
__device__ float  g_qb[MTOT*DM];
__device__ float  g_kb[MTOT*DM];
__device__ float  g_vb[MTOT*DM];
__device__ double g_part[4][32];
// fragment-layout operands for flash attention
__device__ uint32_t g_qfhi[512*8192];   // [(b*16+qt)*16+h] tiles: [ks8][w8][lane32][r4]
__device__ uint32_t g_qflo[512*8192];
__device__ uint32_t g_kfhi[1024*4096];  // [(b*16+h)*32+kt] tiles: [ks8][n8][lane32][r2]
__device__ uint32_t g_kflo[1024*4096];
__device__ uint32_t g_vfhi[1024*2048];  // [(b*16+h)*32+kt] tiles: [j4][n8][lane32][r2]
__device__ uint32_t g_vflo[1024*2048];

// ================= abs-mean + ternarize =================
__global__ void absmean_partial(const float* __restrict__ w0, const float* __restrict__ w1,
                                const float* __restrict__ w2, const float* __restrict__ w3) {
    int mid = blockIdx.x >> 5, blk = blockIdx.x & 31;
    const float* w = (mid == 0) ? w0 : (mid == 1) ? w1 : (mid == 2) ? w2 : w3;
    const int chunk = (DM * DM) / 32;
    const float* p = w + blk * chunk;
    double acc = 0.0;
    for (int i = threadIdx.x; i < chunk; i += blockDim.x) acc += (double)fabsf(p[i]);
    __shared__ double sred[256];
    sred[threadIdx.x] = acc;
    __syncthreads();
    for (int s = 128; s > 0; s >>= 1) {
        if (threadIdx.x < s) sred[threadIdx.x] += sred[threadIdx.x + s];
        __syncthreads();
    }
    if (threadIdx.x == 0) g_part[mid][blk] = sred[0];
}
__global__ void ternarize_k(const float* __restrict__ w0, const float* __restrict__ w1,
                            const float* __restrict__ w2, const float* __restrict__ w3) {
    int idx = blockIdx.x * blockDim.x + threadIdx.x;
    int mid = idx >> 20, off = idx & ((1 << 20) - 1);
    const float* w = (mid == 0) ? w0 : (mid == 1) ? w1 : (mid == 2) ? w2 : w3;
    __shared__ float s_thr;
    if (threadIdx.x == 0) {
        double s = 0.0;
#pragma unroll
        for (int i = 0; i < 32; i++) s += g_part[mid][i];
        s_thr = (float)(s / (double)(DM * DM));
    }
    __syncthreads();
    float t = s_thr;
    float x = w[off];
    float v = (fabsf(x) > t) ? (x > 0.f ? 1.f : -1.f) : 0.f;
    g_twb[mid][off] = __float2bfloat16(v);
}

// ================= combined input limb splits =================
__device__ __forceinline__ void store_bf4(__nv_bfloat16* dst, float a, float b, float c, float d) {
    __nv_bfloat162* p = (__nv_bfloat162*)dst;
    p[0] = __floats2bfloat162_rn(a, b);
    p[1] = __floats2bfloat162_rn(c, d);
}
__global__ void split_all(const float* __restrict__ Q, const float* __restrict__ K,
                          const float* __restrict__ V) {
    const int z = blockIdx.y;
    const float* X = (z == 0) ? Q : (z == 1) ? K : V;
    int i = blockIdx.x * blockDim.x + threadIdx.x;
    int m = i >> 8, j = (i & 255) * 4;
    float4 x = ((const float4*)X)[i];
    float h0 = __bfloat162float(__float2bfloat16(x.x));
    float h1 = __bfloat162float(__float2bfloat16(x.y));
    float h2 = __bfloat162float(__float2bfloat16(x.z));
    float h3 = __bfloat162float(__float2bfloat16(x.w));
    float r0 = x.x - h0, r1 = x.y - h1, r2 = x.z - h2, r3 = x.w - h3;
    if (z == 2) {
        __nv_bfloat16* base = g_sv + (size_t)m * 2048;
        store_bf4(base + j, h0, h1, h2, h3);
        store_bf4(base + 1024 + j, r0, r1, r2, r3);
    } else {
        float m0 = __bfloat162float(__float2bfloat16(r0));
        float m1 = __bfloat162float(__float2bfloat16(r1));
        float m2 = __bfloat162float(__float2bfloat16(r2));
        float m3 = __bfloat162float(__float2bfloat16(r3));
        __nv_bfloat16* base = ((z == 0) ? g_sq : g_sk) + (size_t)m * 3072;
        store_bf4(base + j, h0, h1, h2, h3);
        store_bf4(base + 1024 + j, m0, m1, m2, m3);
        store_bf4(base + 2048 + j, r0 - m0, r1 - m1, r2 - m2, r3 - m3);
    }
}

// ================= GEMM mainloop (R10-proven: BK=64, 2-stage, 2 CTA/SM) ==============
__device__ __forceinline__ void gemm_body(const __nv_bfloat16* __restrict__ A,
                                          const __nv_bfloat16* __restrict__ W,
                                          float* __restrict__ C,
                                          int KA, char* smraw) {
    const int tid = threadIdx.x, lane = tid & 31, wid = tid >> 5;
    const int wm = (wid >> 2) * 64, wn = (wid & 3) * 32;
    const int row0 = blockIdx.y * 128, col0 = blockIdx.x * 128;
    const uint32_t sbase = smem_u32(smraw);

    float acc[4][4][4];
#pragma unroll
    for (int i = 0; i < 4; i++)
#pragma unroll
        for (int j = 0; j < 4; j++)
#pragma unroll
            for (int k = 0; k < 4; k++) acc[i][j][k] = 0.f;

    const int NIT = KA >> 6;

#pragma unroll 1
    for (int pre = 0; pre < 2; pre++) {
        const int k0 = pre * 64;
        const uint32_t sa = sbase + pre * 32768u;
        const uint32_t sb = sa + 16384u;
#pragma unroll
        for (int j = 0; j < 4; j++) {
            int c = tid * 4 + j;
            int r = c >> 3, g = c & 7;
            cp_async16(sa + SW128(r * 128 + g * 16), A + (size_t)(row0 + r) * KA + k0 + g * 8);
            cp_async16(sb + SW128(r * 128 + g * 16), W + (size_t)(col0 + r) * 1024 + (k0 & 1023) + g * 8);
        }
        CP_COMMIT();
    }

    for (int it = 0; it < NIT; it++) {
        CP_WAIT1();
        __syncthreads();
        const uint32_t sa = sbase + (it & 1) * 32768u;
        const uint32_t sb = sa + 16384u;
#pragma unroll
        for (int ks = 0; ks < 4; ks++) {
            uint32_t a[4][4];
#pragma unroll
            for (int mi = 0; mi < 4; mi++)
                ldm_x4(a[mi], sa + SW128((wm + mi * 16 + (lane & 15)) * 128 +
                                         (2 * ks + (lane >> 4)) * 16));
            uint32_t b[2][4];
#pragma unroll
            for (int p = 0; p < 2; p++)
                ldm_x4(b[p], sb + SW128((wn + p * 16 + ((lane >> 4) << 3) + (lane & 7)) * 128 +
                                        (2 * ks + ((lane >> 3) & 1)) * 16));
#pragma unroll
            for (int mi = 0; mi < 4; mi++)
#pragma unroll
                for (int ni = 0; ni < 4; ni++)
                    mma_bf16(acc[mi][ni], a[mi], &b[ni >> 1][(ni & 1) * 2]);
        }
        __syncthreads();
        if (it + 2 < NIT) {
            const int k0 = (it + 2) * 64;
            const uint32_t sa2 = sbase + ((it + 2) & 1) * 32768u;
            const uint32_t sb2 = sa2 + 16384u;
#pragma unroll
            for (int j = 0; j < 4; j++) {
                int c = tid * 4 + j;
                int r = c >> 3, g = c & 7;
                cp_async16(sa2 + SW128(r * 128 + g * 16), A + (size_t)(row0 + r) * KA + k0 + g * 8);
                cp_async16(sb2 + SW128(r * 128 + g * 16), W + (size_t)(col0 + r) * 1024 + (k0 & 1023) + g * 8);
            }
            CP_COMMIT();
        }
    }

#pragma unroll
    for (int mi = 0; mi < 4; mi++)
#pragma unroll
        for (int ni = 0; ni < 4; ni++) {
            int r = row0 + wm + mi * 16 + (lane >> 2);
            int c = col0 + wn + ni * 8 + 2 * (lane & 3);
            *(float2*)&C[(size_t)r * DM + c] = make_float2(acc[mi][ni][0], acc[mi][ni][1]);
            *(float2*)&C[(size_t)(r + 8) * DM + c] = make_float2(acc[mi][ni][2], acc[mi][ni][3]);
        }
}

// mega GEMM: z=0 q (KA=3072 -> g_qb), z=1 k (3072 -> g_kb), z=2 v (2048 -> g_vb)
__global__ __launch_bounds__(256, 2) void gemm_qkv() {
    extern __shared__ char smraw[];
    const int z = blockIdx.z;
    const __nv_bfloat16* A = (z == 0) ? g_sq : (z == 1) ? g_sk : g_sv;
    float* C = (z == 0) ? g_qb : (z == 1) ? g_kb : g_vb;
    gemm_body(A, g_twb[z], C, (z == 2) ? 2048 : 3072, smraw);
}
// output projection GEMM (KA=2048, A=g_sq limbs written by flash, C=out)
__global__ __launch_bounds__(256, 2) void gemm_out(float* __restrict__ out) {
    extern __shared__ char smraw[];
    gemm_body(g_sq, g_twb[3], out, 2048, smraw);
}

// ================= merged fragment writer =================
// grid (32, 16, 6): z = kind*2 + b, kind 0=Q (x<16), 1=K, 2=V; y = head
__global__ __launch_bounds__(256) void frag_writer() {
    __shared__ float tile[128 * 65];
    const int kind = blockIdx.z >> 1, b = blockIdx.z & 1;
    const int h = blockIdx.y;
    const int tid = threadIdx.x;

    if (kind == 0) {
        const int qt = blockIdx.x;
        if (qt >= 16) return;
        for (int idx = tid; idx < 128 * 64; idx += 256) {
            int row = idx >> 6, col = idx & 63;
            tile[row * 65 + col] = g_qb[(size_t)(b * SQ + qt * 128 + row) * DM + h * HD + col];
        }
        __syncthreads();
        size_t base = (size_t)((b * 16 + qt) * 16 + h) * 8192;
        for (int t2 = tid; t2 < 8192; t2 += 256) {
            int r = t2 & 3, lane = (t2 >> 2) & 31, w = (t2 >> 7) & 7, ks = (t2 >> 10) & 7;
            int g = lane >> 2, tig = lane & 3;
            int row = w * 16 + g + 8 * (r & 1);
            int col = ks * 8 + tig + 4 * (r >> 1);
            float v = tile[row * 65 + col] * 0.125f;
            uint32_t hi = cvt_tf32(v);
            g_qfhi[base + t2] = hi;
            g_qflo[base + t2] = cvt_tf32(v - __uint_as_float(hi));
        }
    } else if (kind == 1) {
        const int kt = blockIdx.x;
        for (int idx = tid; idx < 64 * 64; idx += 256) {
            int row = idx >> 6, col = idx & 63;
            tile[row * 65 + col] = g_kb[(size_t)(b * SQ + kt * 64 + row) * DM + h * HD + col];
        }
        __syncthreads();
        size_t base = (size_t)((b * 16 + h) * 32 + kt) * 4096;
        for (int t2 = tid; t2 < 4096; t2 += 256) {
            int r = t2 & 1, lane = (t2 >> 1) & 31, n = (t2 >> 6) & 7, ks = (t2 >> 9) & 7;
            int g = lane >> 2, tig = lane & 3;
            int key = n * 8 + g;
            int d = ks * 8 + tig + 4 * r;
            float v = tile[key * 65 + d];
            uint32_t hi = cvt_tf32(v);
            g_kfhi[base + t2] = hi;
            g_kflo[base + t2] = cvt_tf32(v - __uint_as_float(hi));
        }
    } else {
        const int kt = blockIdx.x;
        for (int idx = tid; idx < 64 * 64; idx += 256) {
            int row = idx >> 6, col = idx & 63;
            tile[row * 65 + col] = g_vb[(size_t)(b * SQ + kt * 64 + row) * DM + h * HD + col];
        }
        __syncthreads();
        size_t base = (size_t)((b * 16 + h) * 32 + kt) * 2048;
        for (int t2 = tid; t2 < 2048; t2 += 256) {
            int r = t2 & 1, lane = (t2 >> 1) & 31, n = (t2 >> 6) & 7, j = (t2 >> 9) & 3;
            int g = lane >> 2, tig = lane & 3;
            int key0 = j * 16 + 2 * tig + 8 * r;
            int d = n * 8 + g;
            float v0 = tile[key0 * 65 + d];
            float v1 = tile[(key0 + 1) * 65 + d];
            float h0 = __bfloat162float(__float2bfloat16(v0));
            float h1 = __bfloat162float(__float2bfloat16(v1));
            g_vfhi[base + t2] = pack_bf16x2(v0, v1);
            g_vflo[base + t2] = pack_bf16x2(v0 - h0, v1 - h1);
        }
    }
}

// ================= flash attention: 32 q-rows/warp, q-tile 256, fused O-split =========
// SMEM: Qhi 64KB (two 128-row frag tiles) | Qlo 64KB | 2 stages x 48KB (K 32K + V 16K)
#define FQ_HI 0u
#define FQ_LO 65536u
#define F_ST  131072u
#define F_STG 49152u
#define F_KHI 0u
#define F_KLO 16384u
#define F_VHI 32768u
#define F_VLO 40960u
__global__ __launch_bounds__(256, 1) void flash_mma3() {
    extern __shared__ char smraw[];
    const uint32_t sbase = smem_u32(smraw);
    const int qt = blockIdx.x, h = blockIdx.y, b = blockIdx.z;
    const int tid = threadIdx.x, lane = tid & 31, wid = tid >> 5;
    const int g = lane >> 2, tig = lane & 3;
    const int tt = wid >> 2;          // which 128-row Q sub-tile this warp reads
    const int ws = (wid & 3) * 2;     // fragment slot base within sub-tile

    const uint32_t* Khi = g_kfhi + (size_t)((b * 16 + h) * 32) * 4096;
    const uint32_t* Klo = g_kflo + (size_t)((b * 16 + h) * 32) * 4096;
    const uint32_t* Vhi = g_vfhi + (size_t)((b * 16 + h) * 32) * 2048;
    const uint32_t* Vlo = g_vflo + (size_t)((b * 16 + h) * 32) * 2048;

    // Q prologue: both 128-row frag tiles (hi+lo), 32 cp.async/thread
#pragma unroll
    for (int t2 = 0; t2 < 2; t2++) {
        const uint32_t* qh = g_qfhi + (size_t)((b * 16 + 2 * qt + t2) * 16 + h) * 8192;
        const uint32_t* ql = g_qflo + (size_t)((b * 16 + 2 * qt + t2) * 16 + h) * 8192;
#pragma unroll
        for (int i = 0; i < 8; i++) {
            int idx = tid + i * 256;
            cp_async16(sbase + FQ_HI + t2 * 32768u + idx * 16, qh + idx * 4);
            cp_async16(sbase + FQ_LO + t2 * 32768u + idx * 16, ql + idx * 4);
        }
    }
    CP_COMMIT();
    {   // stage 0 prefetch
        const uint32_t st = sbase + F_ST;
#pragma unroll
        for (int i = 0; i < 4; i++) {
            int idx = tid + i * 256;
            cp_async16(st + F_KHI + idx * 16, Khi + idx * 4);
            cp_async16(st + F_KLO + idx * 16, Klo + idx * 4);
        }
#pragma unroll
        for (int i = 0; i < 2; i++) {
            int idx = tid + i * 256;
            cp_async16(st + F_VHI + idx * 16, Vhi + idx * 4);
            cp_async16(st + F_VLO + idx * 16, Vlo + idx * 4);
        }
        CP_COMMIT();
    }

    float o[2][8][4];
#pragma unroll
    for (int mi = 0; mi < 2; mi++)
#pragma unroll
        for (int n = 0; n < 8; n++)
#pragma unroll
            for (int k = 0; k < 4; k++) o[mi][n][k] = 0.f;
    float mreg[2][2], lreg[2][2];
#pragma unroll
    for (int mi = 0; mi < 2; mi++) { mreg[mi][0] = mreg[mi][1] = -1e30f; lreg[mi][0] = lreg[mi][1] = 0.f; }

    for (int t = 0; t < 32; t++) {
        CP_WAIT0();
        __syncthreads();
        if (t + 1 < 32) {
            const uint32_t st = sbase + F_ST + ((t + 1) & 1) * F_STG;
            const uint32_t* kh = Khi + (size_t)(t + 1) * 4096;
            const uint32_t* kl = Klo + (size_t)(t + 1) * 4096;
            const uint32_t* vh = Vhi + (size_t)(t + 1) * 2048;
            const uint32_t* vl = Vlo + (size_t)(t + 1) * 2048;
#pragma unroll
            for (int i = 0; i < 4; i++) {
                int idx = tid + i * 256;
                cp_async16(st + F_KHI + idx * 16, kh + idx * 4);
                cp_async16(st + F_KLO + idx * 16, kl + idx * 4);
            }
#pragma unroll
            for (int i = 0; i < 2; i++) {
                int idx = tid + i * 256;
                cp_async16(st + F_VHI + idx * 16, vh + idx * 4);
                cp_async16(st + F_VLO + idx * 16, vl + idx * 4);
            }
            CP_COMMIT();
        }
        const uint32_t soff = F_ST + (t & 1) * F_STG;

        // ---- S = Q K^T (3xTF32), two 16-row groups per warp ----
        float sf[2][8][4];
#pragma unroll
        for (int mi = 0; mi < 2; mi++)
#pragma unroll
            for (int n = 0; n < 8; n++)
#pragma unroll
                for (int k = 0; k < 4; k++) sf[mi][n][k] = 0.f;
#pragma unroll
        for (int ks = 0; ks < 8; ks++) {
            uint4 qa0 = *(const uint4*)(smraw + FQ_HI +
                (((tt * 8 + ks) * 8 + ws) * 32 + lane) * 16);
            uint4 qa1 = *(const uint4*)(smraw + FQ_HI +
                (((tt * 8 + ks) * 8 + ws + 1) * 32 + lane) * 16);
            uint4 ql0 = *(const uint4*)(smraw + FQ_LO +
                (((tt * 8 + ks) * 8 + ws) * 32 + lane) * 16);
            uint4 ql1 = *(const uint4*)(smraw + FQ_LO +
                (((tt * 8 + ks) * 8 + ws + 1) * 32 + lane) * 16);
            uint32_t ah0[4] = {qa0.x, qa0.y, qa0.z, qa0.w};
            uint32_t al0[4] = {ql0.x, ql0.y, ql0.z, ql0.w};
            uint32_t ah1[4] = {qa1.x, qa1.y, qa1.z, qa1.w};
            uint32_t al1[4] = {ql1.x, ql1.y, ql1.z, ql1.w};
#pragma unroll
            for (int n = 0; n < 8; n++) {
                uint2 bh2 = *(const uint2*)(smraw + soff + F_KHI + ((ks * 8 + n) * 32 + lane) * 8);
                uint2 bl2 = *(const uint2*)(smraw + soff + F_KLO + ((ks * 8 + n) * 32 + lane) * 8);
                uint32_t bh[2] = {bh2.x, bh2.y};
                uint32_t bl[2] = {bl2.x, bl2.y};
                mma_tf32(sf[0][n], ah0, bh);
                mma_tf32(sf[0][n], ah0, bl);
                mma_tf32(sf[0][n], al0, bh);
                mma_tf32(sf[1][n], ah1, bh);
                mma_tf32(sf[1][n], ah1, bl);
                mma_tf32(sf[1][n], al1, bh);
            }
        }

        // ---- online softmax per 16-row group ----
#pragma unroll
        for (int mi = 0; mi < 2; mi++) {
            float mx0 = -1e30f, mx1 = -1e30f;
#pragma unroll
            for (int n = 0; n < 8; n++) {
                mx0 = fmaxf(mx0, fmaxf(sf[mi][n][0], sf[mi][n][1]));
                mx1 = fmaxf(mx1, fmaxf(sf[mi][n][2], sf[mi][n][3]));
            }
            mx0 = fmaxf(mx0, __shfl_xor_sync(0xffffffffu, mx0, 1));
            mx0 = fmaxf(mx0, __shfl_xor_sync(0xffffffffu, mx0, 2));
            mx1 = fmaxf(mx1, __shfl_xor_sync(0xffffffffu, mx1, 1));
            mx1 = fmaxf(mx1, __shfl_xor_sync(0xffffffffu, mx1, 2));
            float mn0 = fmaxf(mreg[mi][0], mx0), mn1 = fmaxf(mreg[mi][1], mx1);
            float al0 = __expf(mreg[mi][0] - mn0), al1 = __expf(mreg[mi][1] - mn1);
            float ls0 = 0.f, ls1 = 0.f;
#pragma unroll
            for (int n = 0; n < 8; n++) {
                sf[mi][n][0] = __expf(sf[mi][n][0] - mn0); ls0 += sf[mi][n][0];
                sf[mi][n][1] = __expf(sf[mi][n][1] - mn0); ls0 += sf[mi][n][1];
                sf[mi][n][2] = __expf(sf[mi][n][2] - mn1); ls1 += sf[mi][n][2];
                sf[mi][n][3] = __expf(sf[mi][n][3] - mn1); ls1 += sf[mi][n][3];
            }
            ls0 += __shfl_xor_sync(0xffffffffu, ls0, 1);
            ls0 += __shfl_xor_sync(0xffffffffu, ls0, 2);
            ls1 += __shfl_xor_sync(0xffffffffu, ls1, 1);
            ls1 += __shfl_xor_sync(0xffffffffu, ls1, 2);
            lreg[mi][0] = lreg[mi][0] * al0 + ls0; mreg[mi][0] = mn0;
            lreg[mi][1] = lreg[mi][1] * al1 + ls1; mreg[mi][1] = mn1;
#pragma unroll
            for (int n = 0; n < 8; n++) {
                o[mi][n][0] *= al0; o[mi][n][1] *= al0;
                o[mi][n][2] *= al1; o[mi][n][3] *= al1;
            }
        }

        // ---- O += P V (bf16, 2-limb P x 2-limb V, 3 passes), shared V loads ----
#pragma unroll
        for (int j = 0; j < 4; j++) {
            uint32_t ahp[2][4], alp[2][4];
#pragma unroll
            for (int mi = 0; mi < 2; mi++) {
                float p00 = sf[mi][2 * j][0], p01 = sf[mi][2 * j][1];
                float p10 = sf[mi][2 * j][2], p11 = sf[mi][2 * j][3];
                float p20 = sf[mi][2 * j + 1][0], p21 = sf[mi][2 * j + 1][1];
                float p30 = sf[mi][2 * j + 1][2], p31 = sf[mi][2 * j + 1][3];
                ahp[mi][0] = pack_bf16x2(p00, p01);
                ahp[mi][1] = pack_bf16x2(p10, p11);
                ahp[mi][2] = pack_bf16x2(p20, p21);
                ahp[mi][3] = pack_bf16x2(p30, p31);
                alp[mi][0] = pack_bf16x2(p00 - __bfloat162float(__float2bfloat16(p00)),
                                         p01 - __bfloat162float(__float2bfloat16(p01)));
                alp[mi][1] = pack_bf16x2(p10 - __bfloat162float(__float2bfloat16(p10)),
                                         p11 - __bfloat162float(__float2bfloat16(p11)));
                alp[mi][2] = pack_bf16x2(p20 - __bfloat162float(__float2bfloat16(p20)),
                                         p21 - __bfloat162float(__float2bfloat16(p21)));
                alp[mi][3] = pack_bf16x2(p30 - __bfloat162float(__float2bfloat16(p30)),
                                         p31 - __bfloat162float(__float2bfloat16(p31)));
            }
#pragma unroll
            for (int n = 0; n < 8; n++) {
                uint2 bh2 = *(const uint2*)(smraw + soff + F_VHI + ((j * 8 + n) * 32 + lane) * 8);
                uint2 bl2 = *(const uint2*)(smraw + soff + F_VLO + ((j * 8 + n) * 32 + lane) * 8);
                uint32_t bh[2] = {bh2.x, bh2.y};
                uint32_t bl[2] = {bl2.x, bl2.y};
                mma_bf16(o[0][n], ahp[0], bh);
                mma_bf16(o[0][n], alp[0], bh);
                mma_bf16(o[0][n], ahp[0], bl);
                mma_bf16(o[1][n], ahp[1], bh);
                mma_bf16(o[1][n], alp[1], bh);
                mma_bf16(o[1][n], ahp[1], bl);
            }
        }
    }

    // fused epilogue: 2-limb bf16 split of O straight into g_sq (out-proj input)
#pragma unroll
    for (int mi = 0; mi < 2; mi++) {
        float inv0 = 1.f / lreg[mi][0], inv1 = 1.f / lreg[mi][1];
        int mrow = b * SQ + qt * 256 + wid * 32 + mi * 16 + g;
        __nv_bfloat16* sp0 = g_sq + (size_t)mrow * 2048 + h * HD;
        __nv_bfloat16* sp1 = g_sq + (size_t)(mrow + 8) * 2048 + h * HD;
#pragma unroll
        for (int n = 0; n < 8; n++) {
            int c = n * 8 + 2 * tig;
            float v0 = o[mi][n][0] * inv0, v1 = o[mi][n][1] * inv0;
            float w0 = o[mi][n][2] * inv1, w1 = o[mi][n][3] * inv1;
            float e0 = __bfloat162float(__float2bfloat16(v0));
            float e1 = __bfloat162float(__float2bfloat16(v1));
            float f0 = __bfloat162float(__float2bfloat16(w0));
            float f1 = __bfloat162float(__float2bfloat16(w1));
            *(uint32_t*)(sp0 + c)        = pack_bf16x2(v0, v1);
            *(uint32_t*)(sp0 + 1024 + c) = pack_bf16x2(v0 - e0, v1 - e1);
            *(uint32_t*)(sp1 + c)        = pack_bf16x2(w0, w1);
            *(uint32_t*)(sp1 + 1024 + c) = pack_bf16x2(w0 - f0, w1 - f1);
        }
    }
}

// ================= launcher =================
extern "C" void kernel_launch(void* const* d_in, const int* in_sizes, int n_in,
                              void* d_out, int out_size) {
    (void)in_sizes; (void)n_in; (void)out_size;
    const float* query = (const float*)d_in[0];
    const float* key   = (const float*)d_in[1];
    const float* value = (const float*)d_in[2];
    const float* wq    = (const float*)d_in[3];
    const float* wk    = (const float*)d_in[4];
    const float* wv    = (const float*)d_in[5];
    const float* wo    = (const float*)d_in[6];
    float* out = (float*)d_out;

    const int smem_gemm  = 65536;                 // 2 stages x (16KB A + 16KB W)
    const int smem_flash = 131072 + 2 * 49152;    // 224KB
    cudaFuncSetAttribute(gemm_qkv,   cudaFuncAttributeMaxDynamicSharedMemorySize, smem_gemm);
    cudaFuncSetAttribute(gemm_out,   cudaFuncAttributeMaxDynamicSharedMemorySize, smem_gemm);
    cudaFuncSetAttribute(flash_mma3, cudaFuncAttributeMaxDynamicSharedMemorySize, smem_flash);

    const int nf4 = MTOT * DM / 4;

    absmean_partial<<<128, 256>>>(wq, wk, wv, wo);                    // 1
    ternarize_k<<<(4 * DM * DM) / 256, 256>>>(wq, wk, wv, wo);        // 2
    split_all<<<dim3(nf4 / 256, 3), 256>>>(query, key, value);        // 3
    gemm_qkv<<<dim3(DM / 128, MTOT / 128, 3), 256, smem_gemm>>>();    // 4  <- profiled
    frag_writer<<<dim3(32, 16, 6), 256>>>();                          // 5
    flash_mma3<<<dim3(SQ / 256, NH, NB), 256, smem_flash>>>();        // 6
    gemm_out<<<dim3(DM / 128, MTOT / 128), 256, smem_gemm>>>(out);    // 7
}